// round 1
// baseline (speedup 1.0000x reference)
#include <cuda_runtime.h>
#include <math.h>

// Problem constants (fixed shapes from reference setup_inputs)
#define B_      4
#define C_      256
#define P_      65536          // H*W = 256*256
#define NSEG    32             // object ids 1..32
#define PT      512            // pixels per tile
#define TILES_PER_B (P_ / PT)  // 128
#define NBLK1   (B_ * TILES_PER_B)  // 512 blocks
#define THREADS1 128
#define UNROLL_C 4

// Per-block partial maxima: [block][seg][channel], 512*32*256 floats = 16 MB
__device__ float g_scratch[(size_t)NBLK1 * NSEG * C_];

// ---------------------------------------------------------------------------
// Phase 1: per-tile segmented max over pixels, all 256 channels per block.
// accum stored as int bit-patterns of non-negative floats (clamp-at-0 is free:
// init 0, and for non-negative floats int compare == float compare).
// ---------------------------------------------------------------------------
__global__ __launch_bounds__(THREADS1)
void seg_pool_kernel(const float* __restrict__ enc, const int* __restrict__ masks) {
    __shared__ int accum[C_ * 33];   // [c][id 0..32], stride 33 spreads banks

    const int blk  = blockIdx.x;
    const int b    = blk / TILES_PER_B;
    const int tile = blk % TILES_PER_B;
    const int tid  = threadIdx.x;

    // zero accumulator
    #pragma unroll
    for (int i = tid; i < C_ * 33; i += THREADS1) accum[i] = 0;

    // load 4 mask ids per thread, once, into registers (reused for all channels)
    const int pbase = tile * PT;
    const int4 idv = reinterpret_cast<const int4*>(masks + (size_t)b * P_ + pbase)[tid];
    const int id0 = idv.x, id1 = idv.y, id2 = idv.z, id3 = idv.w;

    __syncthreads();

    const float* encb = enc + (size_t)b * C_ * P_ + pbase;

    for (int c0 = 0; c0 < C_; c0 += UNROLL_C) {
        float4 v[UNROLL_C];
        #pragma unroll
        for (int u = 0; u < UNROLL_C; u++)
            v[u] = reinterpret_cast<const float4*>(encb + (size_t)(c0 + u) * P_)[tid];

        #pragma unroll
        for (int u = 0; u < UNROLL_C; u++) {
            const int base = (c0 + u) * 33;
            int iv;
            iv = __float_as_int(v[u].x); if (iv > accum[base + id0]) atomicMax(&accum[base + id0], iv);
            iv = __float_as_int(v[u].y); if (iv > accum[base + id1]) atomicMax(&accum[base + id1], iv);
            iv = __float_as_int(v[u].z); if (iv > accum[base + id2]) atomicMax(&accum[base + id2], iv);
            iv = __float_as_int(v[u].w); if (iv > accum[base + id3]) atomicMax(&accum[base + id3], iv);
        }
    }
    __syncthreads();

    // flush [seg][c] (drop id 0 = background), coalesced global writes,
    // shared reads accum[c*33 + s + 1] with consecutive c -> distinct banks.
    float* dst = g_scratch + (size_t)blk * (NSEG * C_);
    #pragma unroll
    for (int i = tid; i < NSEG * C_; i += THREADS1) {
        const int s = i >> 8;        // 0..31
        const int c = i & 255;       // 0..255
        dst[i] = __int_as_float(accum[c * 33 + s + 1]);  // already >= 0
    }
}

// ---------------------------------------------------------------------------
// Phase 2: reduce partial maxima across tiles, then MLP + sigmoid.
// One block per (batch, object). 256 threads.
// ---------------------------------------------------------------------------
__global__ __launch_bounds__(256)
void reduce_mlp_kernel(const float* __restrict__ w1, const float* __restrict__ b1,
                       const float* __restrict__ w2, const float* __restrict__ b2,
                       float* __restrict__ out) {
    __shared__ float pooled[C_];
    __shared__ float h[C_ / 2];

    const int blk = blockIdx.x;      // b*NSEG + n
    const int b   = blk / NSEG;
    const int n   = blk % NSEG;
    const int tid = threadIdx.x;     // 0..255 == channel

    // max over this batch's 128 tiles (scratch mostly L2-resident)
    const float* base = g_scratch + ((size_t)b * TILES_PER_B) * (NSEG * C_) + (size_t)n * C_ + tid;
    float m = 0.0f;
    #pragma unroll 8
    for (int t = 0; t < TILES_PER_B; t++)
        m = fmaxf(m, base[(size_t)t * (NSEG * C_)]);
    pooled[tid] = m;
    __syncthreads();

    // h = pooled @ w1 + b1   (w1: [256,128] row-major -> coalesced over tid)
    if (tid < 128) {
        float acc = b1[tid];
        #pragma unroll 8
        for (int c = 0; c < C_; c++)
            acc = fmaf(pooled[c], w1[c * 128 + tid], acc);
        h[tid] = acc;
    }
    __syncthreads();

    // bbox = sigmoid(h @ w2 + b2)   (w2: [128,4])
    if (tid < 4) {
        float acc = b2[tid];
        #pragma unroll 8
        for (int j = 0; j < 128; j++)
            acc = fmaf(h[j], w2[j * 4 + tid], acc);
        out[blk * 4 + tid] = 1.0f / (1.0f + expf(-acc));
    }
}

// ---------------------------------------------------------------------------
extern "C" void kernel_launch(void* const* d_in, const int* in_sizes, int n_in,
                              void* d_out, int out_size) {
    const float* enc   = (const float*)d_in[0];  // [4,256,256,256] f32
    const float* w1    = (const float*)d_in[1];  // [256,128]
    const float* b1    = (const float*)d_in[2];  // [128]
    const float* w2    = (const float*)d_in[3];  // [128,4]
    const float* b2    = (const float*)d_in[4];  // [4]
    const int*   masks = (const int*)d_in[5];    // [4,1,256,256] i32

    seg_pool_kernel<<<NBLK1, THREADS1>>>(enc, masks);
    reduce_mlp_kernel<<<B_ * NSEG, 256>>>(w1, b1, w2, b2, (float*)d_out);
}